// round 8
// baseline (speedup 1.0000x reference)
#include <cuda_runtime.h>
#include <cuda_bf16.h>
#include <cstdint>

#define NB   8192
#define NS   100
#define NE   64
#define NH1  128
#define NH2  64
#define NF   128

#define ASTRIDE 272                 // padded bf16 row stride in bytes (128*2 + 16)
#define A_BYTES (128 * ASTRIDE)     // 34816
#define B2_BYTES (64 * ASTRIDE)     // 17408

// ---- smem byte offsets ----
#define OFF_AH    0                    // A hi  (Kp, later H0)
#define OFF_AL    (OFF_AH + A_BYTES)   // A lo
#define OFF_B1H   (OFF_AL + A_BYTES)   // Wcat^T hi [128h][128f]
#define OFF_B1L   (OFF_B1H + A_BYTES)
#define OFF_B2H   (OFF_B1L + A_BYTES)  // W1^T hi [64j][128h]
#define OFF_B2L   (OFF_B2H + B2_BYTES)
#define OFF_C     (OFF_B2L + B2_BYTES) // c[128] f32
#define OFF_Q     (OFF_C + 512)
#define OFF_W2    (OFF_Q + 256)
#define OFF_B1B   (OFF_W2 + 256)
#define OFF_SCORE (OFF_B1B + 256)      // 128 f32
#define OFF_PART  (OFF_SCORE + 512)    // 128*2 f32
#define OFF_POUT  (OFF_PART + 1024)    // 4*64 f32
#define SMEM_TOTAL (OFF_POUT + 1024)   // = 177920 B

// ---- device scratch: pre-split weights, [n][k] bf16, 136-elem row stride ----
__device__ __nv_bfloat16 g_B1[2][128 * 136];
__device__ __nv_bfloat16 g_B2[2][64 * 136];
__device__ float g_Wq[NE * NH1];    // [e][h] = W0a + W0d

// ================= helpers =================
__device__ __forceinline__ uint32_t smem_u32(const void* p) {
    uint32_t a;
    asm("{ .reg .u64 t; cvta.to.shared.u64 t, %1; cvt.u32.u64 %0, t; }" : "=r"(a) : "l"(p));
    return a;
}
__device__ __forceinline__ void ldsm4(uint32_t* r, uint32_t addr) {
    asm volatile("ldmatrix.sync.aligned.m8n8.x4.shared.b16 {%0,%1,%2,%3}, [%4];"
                 : "=r"(r[0]), "=r"(r[1]), "=r"(r[2]), "=r"(r[3]) : "r"(addr));
}
__device__ __forceinline__ void mma_bf16(float* c, const uint32_t* a, uint32_t b0, uint32_t b1) {
    asm volatile("mma.sync.aligned.m16n8k16.row.col.f32.bf16.bf16.f32 "
                 "{%0,%1,%2,%3}, {%4,%5,%6,%7}, {%8,%9}, {%0,%1,%2,%3};"
                 : "+f"(c[0]), "+f"(c[1]), "+f"(c[2]), "+f"(c[3])
                 : "r"(a[0]), "r"(a[1]), "r"(a[2]), "r"(a[3]), "r"(b0), "r"(b1));
}
// pack (lo -> lower half, hi -> upper half)
__device__ __forceinline__ uint32_t cvt_bf16x2(float lo, float hi) {
    uint32_t r;
    asm("cvt.rn.bf16x2.f32 %0, %1, %2;" : "=r"(r) : "f"(hi), "f"(lo));
    return r;
}
__device__ __forceinline__ void split_pair(float x0, float x1, uint32_t& hi2, uint32_t& lo2) {
    hi2 = cvt_bf16x2(x0, x1);
    float h0 = __uint_as_float(hi2 << 16);
    float h1 = __uint_as_float(hi2 & 0xffff0000u);
    lo2 = cvt_bf16x2(x0 - h0, x1 - h1);
}

// ================= prep: fold + split weights =================
__global__ void prep_kernel(const float* __restrict__ W0, const float* __restrict__ W1) {
    int gid = blockIdx.x * blockDim.x + threadIdx.x;
    if (gid < 16384) {                 // B1: n=h, k=f -> Wcat[f][h]
        int n = gid >> 7, k = gid & 127;
        float v;
        if (k < 64) v = W0[(64 + k) * NH1 + n] - W0[(192 + k) * NH1 + n];
        else        v = W0[(128 + (k - 64)) * NH1 + n];
        __nv_bfloat16 h = __float2bfloat16(v);
        g_B1[0][n * 136 + k] = h;
        g_B1[1][n * 136 + k] = __float2bfloat16(v - __bfloat162float(h));
    } else if (gid < 24576) {          // B2: n=j, k=h -> W1[h][j]
        int i = gid - 16384;
        int n = i >> 7, k = i & 127;
        float v = W1[k * NH2 + n];
        __nv_bfloat16 h = __float2bfloat16(v);
        g_B2[0][n * 136 + k] = h;
        g_B2[1][n * 136 + k] = __float2bfloat16(v - __bfloat162float(h));
    } else if (gid < 32768) {          // Wq = W0a + W0d
        int i = gid - 24576;
        int e = i >> 7, hh = i & 127;
        g_Wq[e * NH1 + hh] = W0[e * NH1 + hh] + W0[(192 + e) * NH1 + hh];
    }
}

// ================= fused kernel: 1 CTA = 1 batch, 256 threads =================
__global__ __launch_bounds__(256, 1)
void din_kernel(const float* __restrict__ q_g,
                const float* __restrict__ keys_g,
                const int*   __restrict__ klen_g,
                const float* __restrict__ b0_g,
                const float* __restrict__ b1_g,
                const float* __restrict__ W2_g,
                const float* __restrict__ b2_g,
                float* __restrict__ out_g,
                float* __restrict__ attn_g) {
    extern __shared__ char smem[];
    const uint32_t sbase = smem_u32(smem);
    float* sC     = (float*)(smem + OFF_C);
    float* sQ     = (float*)(smem + OFF_Q);
    float* sW2    = (float*)(smem + OFF_W2);
    float* sB1b   = (float*)(smem + OFF_B1B);
    float* sScore = (float*)(smem + OFF_SCORE);
    float* sPart  = (float*)(smem + OFF_PART);
    float* sPOut  = (float*)(smem + OFF_POUT);

    const int b = blockIdx.x;
    const int t = threadIdx.x;
    const int lane = t & 31, w = t >> 5;
    const int len = klen_g[b];
    const float b2v = b2_g[0];

    // ---- weight tiles -> smem (straight uint4 copies, L2-hot) ----
    {
        const uint4* s1 = (const uint4*)&g_B1[0][0];
        uint4* d1 = (uint4*)(smem + OFF_B1H);
        #pragma unroll 4
        for (int i = t; i < (2 * A_BYTES) / 16; i += 256) d1[i] = s1[i];
        const uint4* s2 = (const uint4*)&g_B2[0][0];
        uint4* d2 = (uint4*)(smem + OFF_B2H);
        #pragma unroll 4
        for (int i = t; i < (2 * B2_BYTES) / 16; i += 256) d2[i] = s2[i];
    }
    if (t < 64) { sQ[t] = q_g[b * NE + t]; sW2[t] = W2_g[t]; sB1b[t] = b1_g[t]; }
    __syncthreads();   // sQ ready for Kp build

    // ---- c[h] = b0[h] + sum_e q[e] * Wq[e][h] ----
    if (t < NH1) {
        float acc = b0_g[t];
        #pragma unroll 8
        for (int e = 0; e < NE; e++) acc = fmaf(sQ[e], g_Wq[e * NH1 + t], acc);
        sC[t] = acc;
    }

    // ---- A1 = [keys | keys*q] bf16 hi/lo into padded smem ----
    for (int i = t; i < NS * 32; i += 256) {
        int s = i >> 5, p = i & 31;           // element pair (2p, 2p+1)
        float2 kv = *(const float2*)&keys_g[((size_t)b * NS + s) * NE + 2 * p];
        uint32_t hi, lo;
        split_pair(kv.x, kv.y, hi, lo);
        *(uint32_t*)(smem + OFF_AH + s * ASTRIDE + p * 4) = hi;
        *(uint32_t*)(smem + OFF_AL + s * ASTRIDE + p * 4) = lo;
        float q0 = sQ[2 * p], q1 = sQ[2 * p + 1];
        split_pair(kv.x * q0, kv.y * q1, hi, lo);
        *(uint32_t*)(smem + OFF_AH + s * ASTRIDE + 128 + p * 4) = hi;
        *(uint32_t*)(smem + OFF_AL + s * ASTRIDE + 128 + p * 4) = lo;
    }
    // zero pad rows 100..127 (both hi and lo)
    for (int i = t; i < 28 * 17 * 2; i += 256) {
        int m = i / (28 * 17), r = (i % (28 * 17)) / 17, cc = i % 17;
        *(uint4*)(smem + (m ? OFF_AL : OFF_AH) + (100 + r) * ASTRIDE + cc * 16) =
            make_uint4(0, 0, 0, 0);
    }
    __syncthreads();

    // ---- lane geometry for ldmatrix ----
    const uint32_t aRow = lane & 15;
    const uint32_t aCol = ((lane >> 4) & 1) * 16;           // bytes
    const uint32_t bRow = (lane & 7) + ((lane >> 4) & 1) * 8;
    const uint32_t bCol = ((lane >> 3) & 1) * 16;           // bytes

    const int mg = w >> 1, s0 = mg * 32;
    const uint32_t aBaseH0 = sbase + OFF_AH + (s0 + aRow) * ASTRIDE + aCol;
    const uint32_t aBaseH1 = aBaseH0 + 16 * ASTRIDE;
    const uint32_t aBaseL0 = aBaseH0 + A_BYTES;
    const uint32_t aBaseL1 = aBaseH1 + A_BYTES;

    // ================= GEMM1: D1[128s x 128h] = Kp @ Wcat =================
    float acc[16][4];
    {
        const int ng = w & 1, h0 = ng * 64;
        #pragma unroll
        for (int i = 0; i < 16; i++)
            #pragma unroll
            for (int j = 0; j < 4; j++) acc[i][j] = 0.f;

        uint32_t bBaseH[4], bBaseL[4];
        #pragma unroll
        for (int np = 0; np < 4; np++) {
            bBaseH[np] = sbase + OFF_B1H + (h0 + np * 16 + bRow) * ASTRIDE + bCol;
            bBaseL[np] = bBaseH[np] + A_BYTES;
        }

        #pragma unroll
        for (int k = 0; k < 8; k++) {
            const uint32_t ko = k * 32;
            uint32_t ah0[4], ah1[4], al0[4], al1[4];
            ldsm4(ah0, aBaseH0 + ko);
            ldsm4(ah1, aBaseH1 + ko);
            ldsm4(al0, aBaseL0 + ko);
            ldsm4(al1, aBaseL1 + ko);
            uint32_t bh[4][4], bl[4][4];
            #pragma unroll
            for (int np = 0; np < 4; np++) {
                ldsm4(bh[np], bBaseH[np] + ko);
                ldsm4(bl[np], bBaseL[np] + ko);
            }
            #pragma unroll
            for (int np = 0; np < 4; np++) {
                #pragma unroll
                for (int half = 0; half < 2; half++) {
                    const int nt = np * 2 + half;
                    const uint32_t bh0 = bh[np][half * 2], bh1 = bh[np][half * 2 + 1];
                    const uint32_t bl0 = bl[np][half * 2], bl1 = bl[np][half * 2 + 1];
                    mma_bf16(acc[nt],     ah0, bh0, bh1);
                    mma_bf16(acc[nt],     ah0, bl0, bl1);
                    mma_bf16(acc[nt],     al0, bh0, bh1);
                    mma_bf16(acc[8 + nt], ah1, bh0, bh1);
                    mma_bf16(acc[8 + nt], ah1, bl0, bl1);
                    mma_bf16(acc[8 + nt], al1, bh0, bh1);
                }
            }
        }
    }
    __syncthreads();   // done reading A1

    // ---- epilogue1: H0 = relu(D1 + c) -> split bf16 -> A region ----
    {
        const int ng = w & 1, h0 = ng * 64;
        #pragma unroll
        for (int mt = 0; mt < 2; mt++) {
            #pragma unroll
            for (int nt = 0; nt < 8; nt++) {
                const float* c = acc[mt * 8 + nt];
                const int row = s0 + mt * 16 + (lane >> 2);
                const int col = h0 + nt * 8 + (lane & 3) * 2;
                const float c0 = sC[col], c1 = sC[col + 1];
                uint32_t hi, lo;
                split_pair(fmaxf(c[0] + c0, 0.f), fmaxf(c[1] + c1, 0.f), hi, lo);
                *(uint32_t*)(smem + OFF_AH + row * ASTRIDE + col * 2) = hi;
                *(uint32_t*)(smem + OFF_AL + row * ASTRIDE + col * 2) = lo;
                split_pair(fmaxf(c[2] + c0, 0.f), fmaxf(c[3] + c1, 0.f), hi, lo);
                *(uint32_t*)(smem + OFF_AH + (row + 8) * ASTRIDE + col * 2) = hi;
                *(uint32_t*)(smem + OFF_AL + (row + 8) * ASTRIDE + col * 2) = lo;
            }
        }
    }
    __syncthreads();

    // ================= GEMM2: D2[128s x 64j] = H0 @ W1 =================
    float acc2[8][4];
    const int ng2 = w & 1, j0 = ng2 * 32;
    {
        #pragma unroll
        for (int i = 0; i < 8; i++)
            #pragma unroll
            for (int j = 0; j < 4; j++) acc2[i][j] = 0.f;

        uint32_t bBaseH[2], bBaseL[2];
        #pragma unroll
        for (int np = 0; np < 2; np++) {
            bBaseH[np] = sbase + OFF_B2H + (j0 + np * 16 + bRow) * ASTRIDE + bCol;
            bBaseL[np] = bBaseH[np] + B2_BYTES;
        }

        #pragma unroll
        for (int k = 0; k < 8; k++) {
            const uint32_t ko = k * 32;
            uint32_t ah0[4], ah1[4], al0[4], al1[4];
            ldsm4(ah0, aBaseH0 + ko);
            ldsm4(ah1, aBaseH1 + ko);
            ldsm4(al0, aBaseL0 + ko);
            ldsm4(al1, aBaseL1 + ko);
            uint32_t bh[2][4], bl[2][4];
            #pragma unroll
            for (int np = 0; np < 2; np++) {
                ldsm4(bh[np], bBaseH[np] + ko);
                ldsm4(bl[np], bBaseL[np] + ko);
            }
            #pragma unroll
            for (int np = 0; np < 2; np++) {
                #pragma unroll
                for (int half = 0; half < 2; half++) {
                    const int nt = np * 2 + half;
                    const uint32_t bh0 = bh[np][half * 2], bh1 = bh[np][half * 2 + 1];
                    const uint32_t bl0 = bl[np][half * 2], bl1 = bl[np][half * 2 + 1];
                    mma_bf16(acc2[nt],     ah0, bh0, bh1);
                    mma_bf16(acc2[nt],     ah0, bl0, bl1);
                    mma_bf16(acc2[nt],     al0, bh0, bh1);
                    mma_bf16(acc2[4 + nt], ah1, bh0, bh1);
                    mma_bf16(acc2[4 + nt], ah1, bl0, bl1);
                    mma_bf16(acc2[4 + nt], al1, bh0, bh1);
                }
            }
        }
    }

    // ---- epilogue2: scores = sum_j relu(D2 + b1)*W2 ----
    {
        float part[4] = {0.f, 0.f, 0.f, 0.f};   // [mt][rowhalf]
        #pragma unroll
        for (int mt = 0; mt < 2; mt++) {
            #pragma unroll
            for (int nt = 0; nt < 4; nt++) {
                const float* c = acc2[mt * 4 + nt];
                const int col = j0 + nt * 8 + (lane & 3) * 2;
                const float bb0 = sB1b[col], bb1 = sB1b[col + 1];
                const float w0v = sW2[col],  w1v = sW2[col + 1];
                part[mt * 2]     += fmaxf(c[0] + bb0, 0.f) * w0v + fmaxf(c[1] + bb1, 0.f) * w1v;
                part[mt * 2 + 1] += fmaxf(c[2] + bb0, 0.f) * w0v + fmaxf(c[3] + bb1, 0.f) * w1v;
            }
        }
        #pragma unroll
        for (int i = 0; i < 4; i++) {
            float v = part[i];
            v += __shfl_xor_sync(0xffffffffu, v, 1);
            v += __shfl_xor_sync(0xffffffffu, v, 2);
            if ((lane & 3) == 0) {
                const int row = s0 + (i >> 1) * 16 + (lane >> 2) + (i & 1) * 8;
                sPart[row * 2 + ng2] = v;
            }
        }
    }
    __syncthreads();
    if (t < 128) sScore[t] = sPart[t * 2] + sPart[t * 2 + 1] + b2v;
    __syncthreads();

    // ---- masked softmax (warp 0) ----
    if (t < 32) {
        float m = -1e30f;
        for (int s = t; s < NS; s += 32) {
            float v = (s < len) ? sScore[s] : -1e30f;
            m = fmaxf(m, v);
        }
        #pragma unroll
        for (int off = 16; off; off >>= 1) m = fmaxf(m, __shfl_xor_sync(0xffffffffu, m, off));
        float sum = 0.f;
        for (int s = t; s < NS; s += 32) {
            float v = (s < len) ? expf(sScore[s] - m) : 0.f;
            sScore[s] = v;
            sum += v;
        }
        #pragma unroll
        for (int off = 16; off; off >>= 1) sum += __shfl_xor_sync(0xffffffffu, sum, off);
        float inv = 1.f / sum;
        for (int s = t; s < NS; s += 32) sScore[s] *= inv;
    }
    __syncthreads();

    // ---- out[e] = sum_s attn[s] * keys[s][e] (keys L2-hot) ----
    {
        const int e = t & 63, g = t >> 6;
        const float* kb = keys_g + (size_t)b * NS * NE;
        float a = 0.f;
        for (int s = g; s < NS; s += 4) a = fmaf(sScore[s], kb[s * NE + e], a);
        sPOut[g * 64 + e] = a;
    }
    __syncthreads();
    if (t < 64)
        out_g[(size_t)b * NE + t] = sPOut[t] + sPOut[64 + t] + sPOut[128 + t] + sPOut[192 + t];
    if (attn_g && t < NS) attn_g[(size_t)b * NS + t] = sScore[t];
}

extern "C" void kernel_launch(void* const* d_in, const int* in_sizes, int n_in,
                              void* d_out, int out_size) {
    const float* query = (const float*)d_in[0];
    const float* keys  = (const float*)d_in[1];
    const int*   klen  = (const int*)  d_in[2];
    const float* W0    = (const float*)d_in[3];
    const float* b0    = (const float*)d_in[4];
    const float* W1    = (const float*)d_in[5];
    const float* b1    = (const float*)d_in[6];
    const float* W2    = (const float*)d_in[7];
    const float* b2    = (const float*)d_in[8];

    float* outp  = (float*)d_out;
    float* attnp = (out_size >= NB * NE + NB * NS) ? outp + (size_t)NB * NE : nullptr;

    cudaFuncSetAttribute(din_kernel, cudaFuncAttributeMaxDynamicSharedMemorySize, SMEM_TOTAL);

    prep_kernel<<<64, 512>>>(W0, W1);
    din_kernel<<<NB, 256, SMEM_TOTAL>>>(query, keys, klen, b0, b1, W2, b2, outp, attnp);
}